// round 7
// baseline (speedup 1.0000x reference)
#include <cuda_runtime.h>
#include <cuda_fp16.h>
#include <cstdint>

#define NB 32768
#define ND 512
#define NC 527
#define NPAD 576     // 3 * 192

#define NCHUNK 4
#define CROWS (NB / NCHUNK)   // 8192

#define BM 128
#define BN 192
#define BKH 32          // halfs per K-stage
#define RPAD 40         // padded row stride in halfs (80B; conflict-free LDSM)
#define STAGES 4
#define NIT (ND / BKH)  // 16

#define A_STAGE_H (BM * RPAD)   // 5120 halfs
#define B_STAGE_H (BN * RPAD)   // 7680 halfs
#define STAGE_H   (A_STAGE_H + B_STAGE_H)
#define SMEM_DYN  (STAGES * STAGE_H * 2)   // 102,400 B

// Scratch: fp16 copies of X and (padded) W, fp32 logits.
__device__ __half g_Xh[(size_t)NB * ND];     // 32 MB
__device__ __half g_Wh[(size_t)NPAD * ND];   // 0.56 MB (rows >= NC zeroed)
__device__ float  g_LOG[(size_t)NB * NPAD];  // 75.5 MB

// ---------------------------------------------------------------------------
// K0: fp32 -> fp16 conversion for one row chunk (+ W on chunk 0)
// ---------------------------------------------------------------------------
__global__ __launch_bounds__(256)
void k_conv(const float* __restrict__ X, const float* __restrict__ W,
            int rowOff, int doW) {
    const size_t stride = (size_t)gridDim.x * blockDim.x;
    size_t i0 = (size_t)blockIdx.x * blockDim.x + threadIdx.x;

    const size_t base4 = (size_t)rowOff * ND / 4;
    const float4* X4 = (const float4*)X;
    const size_t nx4 = (size_t)CROWS * ND / 4;
    for (size_t j = i0; j < nx4; j += stride) {
        float4 v = X4[base4 + j];
        __half2 h0 = __floats2half2_rn(v.x, v.y);
        __half2 h1 = __floats2half2_rn(v.z, v.w);
        uint2 p;
        p.x = *(uint32_t*)&h0; p.y = *(uint32_t*)&h1;
        *(uint2*)&g_Xh[(base4 + j) * 4] = p;
    }

    if (doW) {
        const size_t nw4 = (size_t)NPAD * ND / 4;
        for (size_t j = i0; j < nw4; j += stride) {
            size_t row = j >> 7;            // 128 float4 per 512-col row
            uint2 p = make_uint2(0u, 0u);
            if (row < NC) {
                float4 v = *(const float4*)&W[j * 4];
                __half2 h0 = __floats2half2_rn(v.x, v.y);
                __half2 h1 = __floats2half2_rn(v.z, v.w);
                p.x = *(uint32_t*)&h0; p.y = *(uint32_t*)&h1;
            }
            *(uint2*)&g_Wh[j * 4] = p;
        }
    }
}

__device__ __forceinline__ void mma_f16(float* c, const uint32_t* a, const uint32_t* b) {
    asm volatile(
        "mma.sync.aligned.m16n8k16.row.col.f32.f16.f16.f32 "
        "{%0,%1,%2,%3}, {%4,%5,%6,%7}, {%8,%9}, {%0,%1,%2,%3};\n"
        : "+f"(c[0]), "+f"(c[1]), "+f"(c[2]), "+f"(c[3])
        : "r"(a[0]), "r"(a[1]), "r"(a[2]), "r"(a[3]), "r"(b[0]), "r"(b[1]));
}

__device__ __forceinline__ void ldsm_x4(uint32_t* r, uint32_t addr) {
    asm volatile("ldmatrix.sync.aligned.m8n8.x4.shared.b16 {%0,%1,%2,%3}, [%4];"
                 : "=r"(r[0]), "=r"(r[1]), "=r"(r[2]), "=r"(r[3]) : "r"(addr));
}

// ---------------------------------------------------------------------------
// K1: fp16 mma GEMM for one row chunk
// ---------------------------------------------------------------------------
__global__ __launch_bounds__(256, 1)
void k_gemm(const __half* __restrict__ Xh, const __half* __restrict__ Wh,
            const float* __restrict__ bias, float* __restrict__ out, int rowOff) {
    extern __shared__ __half smh[];   // [STAGES][A | B], RPAD-padded rows
    __shared__ float sBias[BN];

    const int tid  = threadIdx.x;
    const int lane = tid & 31;
    const int warp = tid >> 5;
    const int wm   = warp & 1;      // 0..1
    const int wn   = warp >> 1;     // 0..3
    const int g    = lane >> 2;     // 0..7
    const int t    = lane & 3;      // 0..3

    const int col0 = blockIdx.x * BN;
    const int row0 = rowOff + blockIdx.y * BM;

    // zero outputs in the very first gemm chunk (runs before any reduce)
    if (rowOff == 0 && blockIdx.x == 0 && blockIdx.y == 0 && tid < 2) out[tid] = 0.0f;

    for (int i = tid; i < BN; i += 256)
        sBias[i] = (col0 + i < NC) ? bias[col0 + i] : 0.0f;

    const int aRow = (lane & 7) + ((lane >> 3) & 1) * 8;
    const int aCol = (lane >> 4) * 8;
    const int bRow = (lane & 7) + (lane >> 4) * 8;
    const int bCol = ((lane >> 3) & 1) * 8;

    const uint32_t smBase = (uint32_t)__cvta_generic_to_shared(smh);

    float acc[4][6][4];
    #pragma unroll
    for (int i = 0; i < 4; i++)
        #pragma unroll
        for (int j = 0; j < 6; j++)
            #pragma unroll
            for (int r = 0; r < 4; r++) acc[i][j][r] = 0.0f;

    auto load_stage = [&](int kt, int buf) {
        __half* sA = smh + buf * STAGE_H;
        __half* sB = sA + A_STAGE_H;
        const __half* Xb = Xh + (size_t)row0 * ND + kt * BKH;
        #pragma unroll
        for (int i = 0; i < 2; i++) {              // A: 512 x 16B chunks / 256 thr
            int id = i * 256 + tid;
            int r = id >> 2, c = (id & 3) * 8;
            uint32_t dst = (uint32_t)__cvta_generic_to_shared(&sA[r * RPAD + c]);
            asm volatile("cp.async.ca.shared.global [%0], [%1], 16;\n"
                         :: "r"(dst), "l"(Xb + (size_t)r * ND + c));
        }
        const __half* Wb = Wh + (size_t)col0 * ND + kt * BKH;
        #pragma unroll
        for (int i = 0; i < 3; i++) {              // B: 768 x 16B chunks / 256 thr
            int id = i * 256 + tid;
            int r = id >> 2, c = (id & 3) * 8;
            uint32_t dst = (uint32_t)__cvta_generic_to_shared(&sB[r * RPAD + c]);
            asm volatile("cp.async.ca.shared.global [%0], [%1], 16;\n"
                         :: "r"(dst), "l"(Wb + (size_t)r * ND + c));
        }
    };

    auto compute_stage = [&](int buf) {
        const uint32_t sA = smBase + (buf * STAGE_H) * 2;
        const uint32_t sB = sA + A_STAGE_H * 2;
        #pragma unroll
        for (int ks = 0; ks < 2; ks++) {           // 2 x k16 per BK=32
            const int k0 = ks * 16;
            uint32_t a[4][4], bf[3][4];
            #pragma unroll
            for (int mt = 0; mt < 4; mt++) {
                int r = wm * 64 + mt * 16 + aRow;
                ldsm_x4(a[mt], sA + (r * RPAD + k0 + aCol) * 2);
            }
            #pragma unroll
            for (int nb = 0; nb < 3; nb++) {       // 2 n-tiles per LDSM
                int c = wn * 48 + nb * 16 + bRow;
                ldsm_x4(bf[nb], sB + (c * RPAD + k0 + bCol) * 2);
            }
            #pragma unroll
            for (int mt = 0; mt < 4; mt++)
                #pragma unroll
                for (int nt = 0; nt < 6; nt++)
                    mma_f16(acc[mt][nt], a[mt], &bf[nt >> 1][(nt & 1) * 2]);
        }
    };

    load_stage(0, 0); asm volatile("cp.async.commit_group;\n");
    load_stage(1, 1); asm volatile("cp.async.commit_group;\n");
    load_stage(2, 2); asm volatile("cp.async.commit_group;\n");

    for (int it = 0; it < NIT; it++) {
        asm volatile("cp.async.wait_group 2;\n");
        __syncthreads();
        if (it + 3 < NIT) load_stage(it + 3, (it + 3) & 3);   // prefetch first
        asm volatile("cp.async.commit_group;\n");
        compute_stage(it & 3);
    }

    // epilogue: bias add + store fp32 logits
    #pragma unroll
    for (int mt = 0; mt < 4; mt++) {
        int gr = row0 + wm * 64 + mt * 16 + g;
        #pragma unroll
        for (int nt = 0; nt < 6; nt++) {
            int ci = wn * 48 + nt * 8 + 2 * t;
            float bv0 = sBias[ci], bv1 = sBias[ci + 1];
            int gc = col0 + ci;
            float2 v0 = make_float2(acc[mt][nt][0] + bv0, acc[mt][nt][1] + bv1);
            float2 v1 = make_float2(acc[mt][nt][2] + bv0, acc[mt][nt][3] + bv1);
            *(float2*)&g_LOG[(size_t)(gr    ) * NPAD + gc] = v0;
            *(float2*)&g_LOG[(size_t)(gr + 8) * NPAD + gc] = v1;
        }
    }
}

// ---------------------------------------------------------------------------
// K2: per-row BCE loss + exact top-k hit rate, one row chunk.
// One warp handles two rows; 2-bit-per-pass radix select.
// ---------------------------------------------------------------------------
__global__ __launch_bounds__(256)
void k_reduce(const float* __restrict__ Y, const float* __restrict__ pw,
              float* __restrict__ out, int rowOff) {
    const int warp = threadIdx.x >> 5;
    const int lane = threadIdx.x & 31;
    const int row0 = rowOff + (blockIdx.x * 8 + warp) * 2;

    unsigned u[2][17];
    unsigned pm[2];
    int      cnt[2];
    float lsum = 0.0f;

    #pragma unroll
    for (int r = 0; r < 2; r++) {
        const float* lg = g_LOG + (size_t)(row0 + r) * NPAD;
        const float* yr = Y + (size_t)(row0 + r) * NC;
        unsigned m = 0;
        #pragma unroll
        for (int i = 0; i < 17; i++) {
            int c = lane + 32 * i;        // max 543 < NPAD: logits in-bounds
            bool v = (c < NC);
            float z  = lg[c];
            float yy = v ? yr[c] : 0.0f;
            float p  = v ? pw[c] : 0.0f;
            float e  = __expf(-fabsf(z));
            float sp = fmaxf(z, 0.0f) + __logf(1.0f + e);   // softplus(z)
            float w  = 1.0f + yy * (p - 1.0f);
            lsum += v ? (w * sp - p * yy * z) : 0.0f;
            m |= (yy != 0.0f) ? (1u << i) : 0u;
            unsigned bb = __float_as_uint(z);
            unsigned uu = bb ^ (((unsigned)((int)bb >> 31)) | 0x80000000u);
            u[r][i] = v ? uu : 0u;        // 0 sorts below every valid key
        }
        pm[r]  = m;
        cnt[r] = __popc(m);
    }

    {
        int q = cnt[0] | (cnt[1] << 16);
        q = __reduce_add_sync(0xffffffffu, q);
        cnt[0] = q & 0xffff; cnt[1] = q >> 16;
    }
    #pragma unroll
    for (int o = 16; o; o >>= 1) lsum += __shfl_xor_sync(0xffffffffu, lsum, o);

    unsigned pre[2] = {0u, 0u};
    int cur[2] = {0x7fffffff, 0x7fffffff};
    int done = 0;
    #pragma unroll 1
    for (int bit = 30; bit >= 0; bit -= 2) {
        const unsigned m1 = 2u << bit;
        const unsigned m0 = 1u << bit;
        int pk[2];
        #pragma unroll
        for (int r = 0; r < 2; r++) {
            const unsigned cH  = pre[r] | m1;
            const unsigned cHB = cH | m0;
            const unsigned cL  = pre[r] | m0;
            int nH = 0, nHB = 0, nL = 0;
            #pragma unroll
            for (int i = 0; i < 17; i++) {
                nH  += (u[r][i] >= cH);
                nHB += (u[r][i] >= cHB);
                nL  += (u[r][i] >= cL);
            }
            pk[r] = nH | (nHB << 10) | (nL << 20);
        }
        pk[0] = __reduce_add_sync(0xffffffffu, pk[0]);
        pk[1] = __reduce_add_sync(0xffffffffu, pk[1]);
        #pragma unroll
        for (int r = 0; r < 2; r++) {
            int nH  = pk[r] & 1023;
            int nHB = (pk[r] >> 10) & 1023;
            int nL  = (pk[r] >> 20) & 1023;
            if (nHB >= cnt[r])      { pre[r] |= m1 | m0; cur[r] = nHB; }
            else if (nH >= cnt[r])  { pre[r] |= m1;      cur[r] = nH; }
            else if (nL >= cnt[r])  { pre[r] |= m0;      cur[r] = nL; }
            done |= (cur[r] == cnt[r]) << r;
        }
        if (done == 3) break;
    }

    int h0 = 0, h1 = 0;
    #pragma unroll
    for (int i = 0; i < 17; i++) {
        h0 += (((pm[0] >> i) & 1u) && (u[0][i] >= pre[0])) ? 1 : 0;
        h1 += (((pm[1] >> i) & 1u) && (u[1][i] >= pre[1])) ? 1 : 0;
    }
    int hh = h0 | (h1 << 16);
    hh = __reduce_add_sync(0xffffffffu, hh);

    if (lane == 0) {
        float sc = (float)(hh & 0xffff) / (float)cnt[0]
                 + (float)(hh >> 16)    / (float)cnt[1];
        atomicAdd(&out[0], lsum * (1.0f / ((float)NB * (float)NC)));
        atomicAdd(&out[1], sc * (1.0f / (float)NB));
    }
}

// ---------------------------------------------------------------------------
// launch: 3-stream chunked pipeline (conv -> gemm -> reduce per row chunk)
// ---------------------------------------------------------------------------
extern "C" void kernel_launch(void* const* d_in, const int* in_sizes, int n_in,
                              void* d_out, int out_size) {
    const float *x = nullptr, *y = nullptr, *W = nullptr, *b = nullptr, *pwt = nullptr;
    int n527 = 0;
    for (int i = 0; i < n_in; i++) {
        if      (in_sizes[i] == NB * ND) x = (const float*)d_in[i];
        else if (in_sizes[i] == NB * NC) y = (const float*)d_in[i];
        else if (in_sizes[i] == NC * ND) W = (const float*)d_in[i];
        else if (in_sizes[i] == NC) {
            if (n527 == 0) b = (const float*)d_in[i];
            else           pwt = (const float*)d_in[i];
            n527++;
        }
    }
    float* out = (float*)d_out;

    static cudaStream_t sConv = nullptr, sRed = nullptr;
    static cudaEvent_t  evFork, evJoin, evC[NCHUNK], evG[NCHUNK];
    static int inited = 0;
    if (!inited) {
        cudaFuncSetAttribute(k_gemm, cudaFuncAttributeMaxDynamicSharedMemorySize, SMEM_DYN);
        cudaStreamCreateWithFlags(&sConv, cudaStreamNonBlocking);
        cudaStreamCreateWithFlags(&sRed,  cudaStreamNonBlocking);
        cudaEventCreateWithFlags(&evFork, cudaEventDisableTiming);
        cudaEventCreateWithFlags(&evJoin, cudaEventDisableTiming);
        for (int c = 0; c < NCHUNK; c++) {
            cudaEventCreateWithFlags(&evC[c], cudaEventDisableTiming);
            cudaEventCreateWithFlags(&evG[c], cudaEventDisableTiming);
        }
        inited = 1;
    }

    __half *xh, *wh;
    cudaGetSymbolAddress((void**)&xh, g_Xh);
    cudaGetSymbolAddress((void**)&wh, g_Wh);

    // fork side streams off the capture (default) stream
    cudaEventRecord(evFork, 0);
    cudaStreamWaitEvent(sConv, evFork, 0);
    cudaStreamWaitEvent(sRed,  evFork, 0);

    // conv chunks on sConv
    for (int c = 0; c < NCHUNK; c++) {
        k_conv<<<512, 256, 0, sConv>>>(x, W, c * CROWS, c == 0);
        cudaEventRecord(evC[c], sConv);
    }

    // gemm chunks on default stream, each gated on its conv
    dim3 gg(NPAD / BN, CROWS / BM);   // (3, 64)
    for (int c = 0; c < NCHUNK; c++) {
        cudaStreamWaitEvent(0, evC[c], 0);
        k_gemm<<<gg, 256, SMEM_DYN>>>(xh, wh, b, out, c * CROWS);
        cudaEventRecord(evG[c], 0);
    }

    // reduce chunks on sRed, each gated on its gemm
    for (int c = 0; c < NCHUNK; c++) {
        cudaStreamWaitEvent(sRed, evG[c], 0);
        k_reduce<<<CROWS / 16, 256, 0, sRed>>>(y, pwt, out, c * CROWS);
    }

    // join back to the capture stream
    cudaEventRecord(evJoin, sRed);
    cudaStreamWaitEvent(0, evJoin, 0);
}